// round 13
// baseline (speedup 1.0000x reference)
#include <cuda_runtime.h>
#include <math.h>

// BFP quant-dequant: x[8192, 12284] fp32, block=8 along last dim.
// step = 2^(frexp_exp(maxabs) - 7); q = clip(rint(x/step), -128, 127); out = q*step.
// 12284 = 3071 float4 per row; block of 8 = float4 pair (f, f^1) held by
// adjacent even/odd lanes -> shared max via shfl_xor(1). Tail float4 3070
// pairs with inactive lane (m=0), matching the reference's zero padding.
//
// R12 probe: identical memory pattern / per-thread code to the 5x-reproduced
// optimum (R2/R5/R9-R11: 121.1-122.5us, DRAM ~81%), but 512-thread CTAs
// (grid 3x8192) instead of 256 (6x8192). Same occupancy math (21 regs,
// 64 warps/SM), half the CTA count -> less launch/drain bookkeeping.
// Expected neutral; closes the last untested cell of the design space.

#define ROWS 8192
#define F4_PER_ROW 3071          // 12284 / 4
#define CTAS_X 3                 // 3 CTAs x 1024 f4-slots = 3072 slots per row
#define TPB 512

__device__ __forceinline__ void qdq4(float4& v, float step, float inv) {
    v.x = fminf(fmaxf(rintf(v.x * inv), -128.0f), 127.0f) * step;
    v.y = fminf(fmaxf(rintf(v.y * inv), -128.0f), 127.0f) * step;
    v.z = fminf(fmaxf(rintf(v.z * inv), -128.0f), 127.0f) * step;
    v.w = fminf(fmaxf(rintf(v.w * inv), -128.0f), 127.0f) * step;
}

__device__ __forceinline__ float amax4(const float4& v) {
    return fmaxf(fmaxf(fabsf(v.x), fabsf(v.y)), fmaxf(fabsf(v.z), fabsf(v.w)));
}

__device__ __forceinline__ void make_steps(float m, float& step, float& inv) {
    // m >= 0. For normal m: frexp exponent e = exp_field - 126.
    // step = 2^(e-7) -> field = ef - 6 ; inv = 2^(7-e) -> field = 260 - ef.
    unsigned ef = __float_as_uint(m) >> 23;
    if (ef >= 7u && ef <= 253u) {
        step = __uint_as_float((ef - 6u) << 23);
        inv  = __uint_as_float((260u - ef) << 23);
    } else {
        int e; frexpf(m, &e);          // exact fallback (m==0 or extreme exponent)
        step = ldexpf(1.0f, e - 7);
        inv  = ldexpf(1.0f, 7 - e);
    }
}

__global__ __launch_bounds__(TPB)
void bfp_kernel(const float4* __restrict__ x, float4* __restrict__ out) {
    const int row = blockIdx.y;
    const int f0  = blockIdx.x * (2 * TPB) + threadIdx.x;  // <= 2559, always valid
    const int f1  = f0 + TPB;                              // invalid only when == 3071
    const size_t rb = (size_t)row * F4_PER_ROW;

    const bool vb = (f1 < F4_PER_ROW);

    float4 a = __ldcs(&x[rb + f0]);
    float4 b = make_float4(0.f, 0.f, 0.f, 0.f);
    if (vb) b = __ldcs(&x[rb + f1]);

    float ma = amax4(a);
    float mb = amax4(b);

    // Partner half-block lives in adjacent lane (f and f^1 differ in bit 0).
    ma = fmaxf(ma, __shfl_xor_sync(0xFFFFFFFFu, ma, 1));
    mb = fmaxf(mb, __shfl_xor_sync(0xFFFFFFFFu, mb, 1));

    float sa, ia, sb, ib;
    make_steps(ma, sa, ia);
    make_steps(mb, sb, ib);

    qdq4(a, sa, ia);
    qdq4(b, sb, ib);

    __stcs(&out[rb + f0], a);
    if (vb) __stcs(&out[rb + f1], b);
}

extern "C" void kernel_launch(void* const* d_in, const int* in_sizes, int n_in,
                              void* d_out, int out_size) {
    const float4* x = (const float4*)d_in[0];
    float4* out = (float4*)d_out;
    dim3 grid(CTAS_X, ROWS);
    bfp_kernel<<<grid, TPB>>>(x, out);
}

// round 14
// speedup vs baseline: 1.0026x; 1.0026x over previous
#include <cuda_runtime.h>
#include <math.h>

// BFP quant-dequant: x[8192, 12284] fp32, block=8 along last dim.
// step = 2^(frexp_exp(maxabs) - 7); q = clip(rint(x/step), -128, 127); out = q*step.
// 12284 = 3071 float4 per row; block of 8 = float4 pair (f, f^1) held by
// adjacent even/odd lanes -> shared max via shfl_xor(1). Tail float4 3070
// pairs with inactive lane (m=0), matching the reference's zero padding.
//
// SESSION FINAL — converged optimum, validated 6x (R2/R5/R9/R10/R11/R12-equiv)
// at 121.1-122.5us wall, ncu 113.5-114.4us, DRAM 80.4-81.2% (~6.6 TB/s, 83%
// of spec), rel_err 0.0:
//   flat 6x8192 grid, 256 threads, MLP-2, perfect sector coalescing,
//   evict-first streaming hints, 21 regs / ~80% occupancy.
// Full design-space sweep: MLP-4 flat/looped/low-occ regressed (R3/R6/R7);
// 512-thread CTAs neutral (R13, occ 74% yet DRAM unchanged -> bus-limited);
// LDG.256 infeasible (odd-row bases 16B-aligned); phase separation / raster
// swap / stwt theory-rejected. Residual ~19% DRAM idle = HBM R/W turnaround
// on a 1:1 mixed stream — invariant across all variants: the device ceiling.

#define ROWS 8192
#define F4_PER_ROW 3071          // 12284 / 4
#define CTAS_X 6                 // 6 * 512 = 3072 float4 slots per row

__device__ __forceinline__ void qdq4(float4& v, float step, float inv) {
    v.x = fminf(fmaxf(rintf(v.x * inv), -128.0f), 127.0f) * step;
    v.y = fminf(fmaxf(rintf(v.y * inv), -128.0f), 127.0f) * step;
    v.z = fminf(fmaxf(rintf(v.z * inv), -128.0f), 127.0f) * step;
    v.w = fminf(fmaxf(rintf(v.w * inv), -128.0f), 127.0f) * step;
}

__device__ __forceinline__ float amax4(const float4& v) {
    return fmaxf(fmaxf(fabsf(v.x), fabsf(v.y)), fmaxf(fabsf(v.z), fabsf(v.w)));
}

__device__ __forceinline__ void make_steps(float m, float& step, float& inv) {
    // m >= 0. For normal m: frexp exponent e = exp_field - 126.
    // step = 2^(e-7) -> field = ef - 6 ; inv = 2^(7-e) -> field = 260 - ef.
    unsigned ef = __float_as_uint(m) >> 23;
    if (ef >= 7u && ef <= 253u) {
        step = __uint_as_float((ef - 6u) << 23);
        inv  = __uint_as_float((260u - ef) << 23);
    } else {
        int e; frexpf(m, &e);          // exact fallback (m==0 or extreme exponent)
        step = ldexpf(1.0f, e - 7);
        inv  = ldexpf(1.0f, 7 - e);
    }
}

__global__ void bfp_kernel(const float4* __restrict__ x, float4* __restrict__ out) {
    const int row = blockIdx.y;
    const int f0  = blockIdx.x * 512 + threadIdx.x;   // <= 2815, always valid
    const int f1  = f0 + 256;                         // invalid only when == 3071
    const size_t rb = (size_t)row * F4_PER_ROW;

    const bool vb = (f1 < F4_PER_ROW);

    float4 a = __ldcs(&x[rb + f0]);
    float4 b = make_float4(0.f, 0.f, 0.f, 0.f);
    if (vb) b = __ldcs(&x[rb + f1]);

    float ma = amax4(a);
    float mb = amax4(b);

    // Partner half-block lives in adjacent lane (f and f^1 differ in bit 0).
    ma = fmaxf(ma, __shfl_xor_sync(0xFFFFFFFFu, ma, 1));
    mb = fmaxf(mb, __shfl_xor_sync(0xFFFFFFFFu, mb, 1));

    float sa, ia, sb, ib;
    make_steps(ma, sa, ia);
    make_steps(mb, sb, ib);

    qdq4(a, sa, ia);
    qdq4(b, sb, ib);

    __stcs(&out[rb + f0], a);
    if (vb) __stcs(&out[rb + f1], b);
}

extern "C" void kernel_launch(void* const* d_in, const int* in_sizes, int n_in,
                              void* d_out, int out_size) {
    const float4* x = (const float4*)d_in[0];
    float4* out = (float4*)d_out;
    dim3 grid(CTAS_X, ROWS);
    bfp_kernel<<<grid, 256>>>(x, out);
}